// round 12
// baseline (speedup 1.0000x reference)
#include <cuda_runtime.h>
#include <cuda_fp16.h>
#include <cstdint>

#define C_DIM   256
#define MAXN    100000
#define EPS_LN  1e-5f

typedef __half f16;

// ---------------- device scratch ----------------
__device__ float g_agg  [MAXN * C_DIM];
__device__ float g_cnt_i[MAXN];
__device__ float g_cnt_u[MAXN];

__device__ __align__(16) f16 g_xu_a[MAXN * C_DIM];
__device__ __align__(16) f16 g_xi_a[MAXN * C_DIM];
__device__ __align__(16) f16 g_xu_b[MAXN * C_DIM];
__device__ __align__(16) f16 g_xi_b[MAXN * C_DIM];
__device__ __align__(16) f16 g_h_f [MAXN * C_DIM];
__device__ __align__(16) f16 g_a_f [MAXN * C_DIM];
__device__ __align__(16) f16 g_p_f [MAXN * C_DIM];

// per conv: W1T[256,256] | W2T[256,256] | WCAT[256,512]  (K-major [n,k])
#define WSTRIDE (262144)
__device__ __align__(16) f16 g_w[4 * WSTRIDE];

// ---------------- helpers ----------------
__device__ __forceinline__ uint32_t smem_u32(const void* p) {
    uint32_t a;
    asm("{ .reg .u64 t; cvta.to.shared.u64 t, %1; cvt.u32.u64 %0, t; }" : "=r"(a) : "l"(p));
    return a;
}
__device__ __forceinline__ void cp16(uint32_t s, const void* g) {
    asm volatile("cp.async.cg.shared.global [%0], [%1], 16;" :: "r"(s), "l"(g));
}
__device__ __forceinline__ void cp_commit() { asm volatile("cp.async.commit_group;" ::: "memory"); }
template<int N> __device__ __forceinline__ void cp_wait() {
    asm volatile("cp.async.wait_group %0;" :: "n"(N) : "memory");
}
#define SW128(o) ((o) ^ (((o) >> 3) & 0x70))

__device__ __forceinline__ uint32_t pack_h2(float a, float b) {
    __half2 t = __halves2half2(__float2half_rn(a), __float2half_rn(b));
    return *reinterpret_cast<uint32_t*>(&t);
}

#define LDSM4(r0, r1, r2, r3, addr) \
    asm volatile("ldmatrix.sync.aligned.m8n8.x4.shared.b16 {%0,%1,%2,%3}, [%4];" \
                 : "=r"(r0), "=r"(r1), "=r"(r2), "=r"(r3) : "r"(addr))

#define MMA16816F(d, a, b0, b1) \
    asm volatile("mma.sync.aligned.m16n8k16.row.col.f32.f16.f16.f32 " \
                 "{%0,%1,%2,%3}, {%4,%5,%6,%7}, {%8,%9}, {%0,%1,%2,%3};" \
                 : "+f"((d)[0]), "+f"((d)[1]), "+f"((d)[2]), "+f"((d)[3]) \
                 : "r"((a)[0]), "r"((a)[1]), "r"((a)[2]), "r"((a)[3]), \
                   "r"(b0), "r"(b1))

__device__ __forceinline__ float warp_sum(float v) {
#pragma unroll
    for (int o = 16; o > 0; o >>= 1) v += __shfl_xor_sync(0xffffffffu, v, o);
    return v;
}

// ---------------- 128x128 warp-MMA GEMM, f16 out ----------------
// out[M,256] = f16(A[M,256] @ B^T + bias [relu]); B K-major [n,256].
#define CHUNK_BYTES 32768
#define GEMM_SMEM   (2 * CHUNK_BYTES)

__device__ __forceinline__ void gemm_load_chunk(
    uint32_t sbuf, int tid, int m0, int n0, int M, int c,
    const f16* Af, const f16* Bf)
{
    const int k0 = c * 64;
#pragma unroll
    for (int i = 0; i < 4; i++) {
        int idx = tid + i * 256;
        int r = idx >> 3, u = idx & 7;
        int rg = min(m0 + r, M - 1);
        uint32_t so = SW128((uint32_t)(r * 128 + u * 16));
        cp16(sbuf + so, (const char*)(Af + (size_t)rg * C_DIM + k0) + u * 16);
    }
#pragma unroll
    for (int i = 0; i < 4; i++) {
        int idx = tid + i * 256;
        int r = idx >> 3, u = idx & 7;
        uint32_t so = SW128((uint32_t)(r * 128 + u * 16));
        cp16(sbuf + 16384 + so, (const char*)(Bf + (size_t)(n0 + r) * C_DIM + k0) + u * 16);
    }
}

template<int RELU>
__global__ __launch_bounds__(256, 2)
void gemm_h(const f16* __restrict__ Af, const f16* __restrict__ Bf,
            const float* __restrict__ bias, f16* __restrict__ outH, int M)
{
    extern __shared__ char smem[];
    const uint32_t sb = smem_u32(smem);
    const int tid  = threadIdx.x;
    const int lane = tid & 31;
    const int wid  = tid >> 5;
    const int wm   = wid >> 2;
    const int wn   = wid & 3;
    const int m0   = blockIdx.x * 128;
    const int n0   = blockIdx.y * 128;

    const uint32_t aOff = (uint32_t)((wm * 64 + (lane & 15)) * 128 + ((lane >> 4) << 4));
    const uint32_t bOff = (uint32_t)((wn * 32 + (lane & 7) + ((lane >> 4) << 3)) * 128
                                     + (((lane >> 3) & 1) << 4));

    float D[4][4][4];
#pragma unroll
    for (int g = 0; g < 4; g++)
#pragma unroll
        for (int n = 0; n < 4; n++)
#pragma unroll
            for (int q = 0; q < 4; q++) D[g][n][q] = 0.f;

    gemm_load_chunk(sb, tid, m0, n0, M, 0, Af, Bf);
    cp_commit();

#pragma unroll
    for (int c = 0; c < 4; c++) {
        if (c + 1 < 4) {
            gemm_load_chunk(sb + (uint32_t)((c + 1) & 1) * CHUNK_BYTES,
                            tid, m0, n0, M, c + 1, Af, Bf);
            cp_commit();
            cp_wait<1>();
        } else {
            cp_wait<0>();
        }
        __syncthreads();

        const uint32_t base = sb + (uint32_t)(c & 1) * CHUNK_BYTES;
#pragma unroll
        for (int ks = 0; ks < 4; ks++) {
            const uint32_t kb = (uint32_t)(ks * 32);
            uint32_t af[4][4];
#pragma unroll
            for (int g = 0; g < 4; g++) {
                uint32_t sw = SW128(aOff + (uint32_t)(g * 2048) + kb);
                LDSM4(af[g][0], af[g][1], af[g][2], af[g][3], base + sw);
            }
            uint32_t bh[2][4];
#pragma unroll
            for (int p = 0; p < 2; p++) {
                uint32_t sw = SW128(bOff + (uint32_t)(p * 2048) + kb);
                LDSM4(bh[p][0], bh[p][1], bh[p][2], bh[p][3], base + 16384 + sw);
            }
#pragma unroll
            for (int g = 0; g < 4; g++) {
#pragma unroll
                for (int n = 0; n < 4; n++) {
                    const int p = n >> 1, rb = (n & 1) * 2;
                    MMA16816F(D[g][n], af[g], bh[p][rb], bh[p][rb + 1]);
                }
            }
        }
        __syncthreads();
    }

#pragma unroll
    for (int g = 0; g < 4; g++) {
#pragma unroll
        for (int n = 0; n < 4; n++) {
            int r0  = m0 + wm * 64 + g * 16 + (lane >> 2);
            int col = n0 + wn * 32 + n * 8 + (lane & 3) * 2;
            float2 bv = *(const float2*)(bias + col);
            float v0 = D[g][n][0] + bv.x, v1 = D[g][n][1] + bv.y;
            float v2 = D[g][n][2] + bv.x, v3 = D[g][n][3] + bv.y;
            if (RELU) {
                v0 = fmaxf(v0, 0.f); v1 = fmaxf(v1, 0.f);
                v2 = fmaxf(v2, 0.f); v3 = fmaxf(v3, 0.f);
            }
            if (r0 < M)
                *(uint32_t*)(outH + (size_t)r0 * C_DIM + col) = pack_h2(v0, v1);
            if (r0 + 8 < M)
                *(uint32_t*)(outH + (size_t)(r0 + 8) * C_DIM + col) = pack_h2(v2, v3);
        }
    }
}

// ---------------- fused K=512 GEMM + LayerNorm + relu ----------------
// new = [Ax | Aa] @ Bcat^T + lin_b ; out = relu(LN(new) * gN + bN)
// Block 128(M) x 256(N full), 512 threads, 16 warps (4m x 4n), warp tile 32x64.
// Bcat: [256, 512] K-major f16 (rows = out cols, k 0-255 -> Wx, 256-511 -> Wa).
#define FCHUNK 49152                   // A 16K | B 32K
#define FSTAGE_STRIDE 264
#define FUSED_SMEM (128 * FSTAGE_STRIDE * 4)   // 135168 >= 2*FCHUNK

__device__ __forceinline__ void fused_load_chunk(
    uint32_t sbuf, int tid, int m0, int M, int c,
    const f16* Ax, const f16* Aa, const f16* Bc)
{
    const f16* ap = (c < 4) ? Ax : Aa;
    const int  ka = (c < 4) ? c * 64 : (c - 4) * 64;
#pragma unroll
    for (int i = 0; i < 2; i++) {                 // A: 128 rows x 128B
        int idx = tid + i * 512;
        int r = idx >> 3, u = idx & 7;
        int rg = min(m0 + r, M - 1);
        uint32_t so = SW128((uint32_t)(r * 128 + u * 16));
        cp16(sbuf + so, (const char*)(ap + (size_t)rg * C_DIM + ka) + u * 16);
    }
#pragma unroll
    for (int i = 0; i < 4; i++) {                 // B: 256 rows x 128B
        int idx = tid + i * 512;
        int r = idx >> 3, u = idx & 7;
        uint32_t so = SW128((uint32_t)(r * 128 + u * 16));
        cp16(sbuf + 16384 + so, (const char*)(Bc + (size_t)r * 512 + c * 64) + u * 16);
    }
}

__global__ __launch_bounds__(512, 1)
void gemm_ln(const f16* __restrict__ Ax, const f16* __restrict__ Aa,
             const f16* __restrict__ Bc, const float* __restrict__ linb,
             const float* __restrict__ gN, const float* __restrict__ bN,
             float* __restrict__ outF, f16* __restrict__ outH, int M)
{
    extern __shared__ char smem[];
    const uint32_t sb = smem_u32(smem);
    const int tid  = threadIdx.x;
    const int lane = tid & 31;
    const int wid  = tid >> 5;
    const int wm   = wid >> 2;          // 0..3 (32-row groups)
    const int wn   = wid & 3;           // 0..3 (64-col groups)
    const int m0   = blockIdx.x * 128;

    const uint32_t aOff = (uint32_t)((wm * 32 + (lane & 15)) * 128 + ((lane >> 4) << 4));
    const uint32_t bOff = (uint32_t)((wn * 64 + (lane & 7) + ((lane >> 4) << 3)) * 128
                                     + (((lane >> 3) & 1) << 4));

    float D[2][8][4];
#pragma unroll
    for (int g = 0; g < 2; g++)
#pragma unroll
        for (int n = 0; n < 8; n++)
#pragma unroll
            for (int q = 0; q < 4; q++) D[g][n][q] = 0.f;

    fused_load_chunk(sb, tid, m0, M, 0, Ax, Aa, Bc);
    cp_commit();

#pragma unroll
    for (int c = 0; c < 8; c++) {
        if (c + 1 < 8) {
            fused_load_chunk(sb + (uint32_t)((c + 1) & 1) * FCHUNK,
                             tid, m0, M, c + 1, Ax, Aa, Bc);
            cp_commit();
            cp_wait<1>();
        } else {
            cp_wait<0>();
        }
        __syncthreads();

        const uint32_t base = sb + (uint32_t)(c & 1) * FCHUNK;
#pragma unroll
        for (int ks = 0; ks < 4; ks++) {
            const uint32_t kb = (uint32_t)(ks * 32);
            uint32_t af[2][4];
#pragma unroll
            for (int g = 0; g < 2; g++) {
                uint32_t sw = SW128(aOff + (uint32_t)(g * 2048) + kb);
                LDSM4(af[g][0], af[g][1], af[g][2], af[g][3], base + sw);
            }
            uint32_t bh[4][4];
#pragma unroll
            for (int p = 0; p < 4; p++) {
                uint32_t sw = SW128(bOff + (uint32_t)(p * 2048) + kb);
                LDSM4(bh[p][0], bh[p][1], bh[p][2], bh[p][3], base + 16384 + sw);
            }
#pragma unroll
            for (int g = 0; g < 2; g++) {
#pragma unroll
                for (int n = 0; n < 8; n++) {
                    const int p = n >> 1, rb = (n & 1) * 2;
                    MMA16816F(D[g][n], af[g], bh[p][rb], bh[p][rb + 1]);
                }
            }
        }
        __syncthreads();
    }

    // ---- stage D + lin_b into smem (full 128x256 rows) ----
    float* stage = (float*)smem;
#pragma unroll
    for (int g = 0; g < 2; g++) {
#pragma unroll
        for (int n = 0; n < 8; n++) {
            int r0  = wm * 32 + g * 16 + (lane >> 2);
            int col = wn * 64 + n * 8 + (lane & 3) * 2;
            float2 bv = *(const float2*)(linb + col);
            *(float2*)(stage + r0 * FSTAGE_STRIDE + col) =
                make_float2(D[g][n][0] + bv.x, D[g][n][1] + bv.y);
            *(float2*)(stage + (r0 + 8) * FSTAGE_STRIDE + col) =
                make_float2(D[g][n][2] + bv.x, D[g][n][3] + bv.y);
        }
    }
    __syncthreads();

    // ---- LN + relu: warp w handles rows w*8 .. w*8+7 ----
#pragma unroll
    for (int rr = 0; rr < 8; rr++) {
        int row = wid * 8 + rr;
        int grow = m0 + row;
        if (grow >= M) continue;
        const float* rp = stage + row * FSTAGE_STRIDE + lane * 8;
        float v[8];
#pragma unroll
        for (int i = 0; i < 4; i++) v[i] = rp[i];
#pragma unroll
        for (int i = 0; i < 4; i++) v[4 + i] = rp[4 + i];
        float s1 = 0.f;
#pragma unroll
        for (int i = 0; i < 8; i++) s1 += v[i];
        float mean = warp_sum(s1) * (1.f / 256.f);
        float s2 = 0.f;
#pragma unroll
        for (int i = 0; i < 8; i++) { float t = v[i] - mean; s2 += t * t; }
        float inv = rsqrtf(warp_sum(s2) * (1.f / 256.f) + EPS_LN);
        int c0 = lane * 8;
        float4 g0 = *(const float4*)(gN + c0), g1 = *(const float4*)(gN + c0 + 4);
        float4 e0 = *(const float4*)(bN + c0), e1 = *(const float4*)(bN + c0 + 4);
        float o[8];
        o[0] = fmaxf((v[0] - mean) * inv * g0.x + e0.x, 0.f);
        o[1] = fmaxf((v[1] - mean) * inv * g0.y + e0.y, 0.f);
        o[2] = fmaxf((v[2] - mean) * inv * g0.z + e0.z, 0.f);
        o[3] = fmaxf((v[3] - mean) * inv * g0.w + e0.w, 0.f);
        o[4] = fmaxf((v[4] - mean) * inv * g1.x + e1.x, 0.f);
        o[5] = fmaxf((v[5] - mean) * inv * g1.y + e1.y, 0.f);
        o[6] = fmaxf((v[6] - mean) * inv * g1.z + e1.z, 0.f);
        o[7] = fmaxf((v[7] - mean) * inv * g1.w + e1.w, 0.f);
        if (outF) {
            float4* op = (float4*)(outF + (size_t)grow * C_DIM + c0);
            op[0] = make_float4(o[0], o[1], o[2], o[3]);
            op[1] = make_float4(o[4], o[5], o[6], o[7]);
        } else {
            *(uint4*)(outH + (size_t)grow * C_DIM + c0) =
                make_uint4(pack_h2(o[0], o[1]), pack_h2(o[2], o[3]),
                           pack_h2(o[4], o[5]), pack_h2(o[6], o[7]));
        }
    }
}

// ---------------- aux kernels ----------------
__global__ void f32_to_f16_kernel(const float* __restrict__ x,
                                  f16* __restrict__ out, int n4)
{
    int idx = blockIdx.x * blockDim.x + threadIdx.x;
    if (idx >= n4) return;
    float4 v = ((const float4*)x)[idx];
    *(uint2*)(out + (size_t)idx * 4) = make_uint2(pack_h2(v.x, v.y), pack_h2(v.z, v.w));
}

// W [256(k),256(n)] row-major -> out[n*256+k]
__global__ void convert_w256_kernel(const float* __restrict__ W, f16* __restrict__ out)
{
    int idx = blockIdx.x * blockDim.x + threadIdx.x;
    if (idx >= 65536) return;
    int n = idx >> 8, k = idx & 255;
    out[idx] = __float2half_rn(W[(size_t)k * 256 + n]);
}

// lin_w [512(k),256(n)] row-major -> out[n*512+k]
__global__ void convert_w512_kernel(const float* __restrict__ W, f16* __restrict__ out)
{
    int idx = blockIdx.x * blockDim.x + threadIdx.x;
    if (idx >= 131072) return;
    int n = idx >> 9, k = idx & 511;
    out[idx] = __float2half_rn(W[(size_t)k * 256 + n]);
}

__global__ void count_kernel(const int* __restrict__ dst, float* __restrict__ cnt, int nE)
{
    int i = blockIdx.x * blockDim.x + threadIdx.x;
    if (i < nE) atomicAdd(cnt + __ldg(dst + i), 1.0f);
}

__global__ void edge_msg_kernel(const f16* __restrict__ xsrc,
                                const f16* __restrict__ Pn,
                                const int* __restrict__ ei,
                                const float* __restrict__ gg,
                                const float* __restrict__ bb,
                                float* __restrict__ agg, int nE)
{
    int w = (blockIdx.x * blockDim.x + threadIdx.x) >> 5;
    int lane = threadIdx.x & 31;
    if (w >= nE) return;
    int s = __ldg(ei + w);
    int d = __ldg(ei + nE + w);
    int c0 = lane << 3;

    uint4 xv = *(const uint4*)(xsrc + (size_t)s * C_DIM + c0);
    uint4 pv = *(const uint4*)(Pn   + (size_t)d * C_DIM + c0);
    const __half2* xh = (const __half2*)&xv;
    const __half2* ph = (const __half2*)&pv;
    float r[8];
#pragma unroll
    for (int i = 0; i < 4; i++) {
        float2 xf = __half22float2(xh[i]);
        float2 pf = __half22float2(ph[i]);
        r[i * 2]     = xf.x - pf.x;
        r[i * 2 + 1] = xf.y - pf.y;
    }
    float s1 = 0.f;
#pragma unroll
    for (int i = 0; i < 8; i++) s1 += r[i];
    float mean = warp_sum(s1) * (1.f / 256.f);
    float s2 = 0.f;
#pragma unroll
    for (int i = 0; i < 8; i++) { float t = r[i] - mean; s2 += t * t; }
    float inv = rsqrtf(warp_sum(s2) * (1.f / 256.f) + EPS_LN);
    float4 g0 = *(const float4*)(gg + c0), g1 = *(const float4*)(gg + c0 + 4);
    float4 e0 = *(const float4*)(bb + c0), e1 = *(const float4*)(bb + c0 + 4);
    float m0v = (r[0] - mean) * inv * g0.x + e0.x;
    float m1v = (r[1] - mean) * inv * g0.y + e0.y;
    float m2v = (r[2] - mean) * inv * g0.z + e0.z;
    float m3v = (r[3] - mean) * inv * g0.w + e0.w;
    float m4v = (r[4] - mean) * inv * g1.x + e1.x;
    float m5v = (r[5] - mean) * inv * g1.y + e1.y;
    float m6v = (r[6] - mean) * inv * g1.z + e1.z;
    float m7v = (r[7] - mean) * inv * g1.w + e1.w;
    float* dstp = agg + (size_t)d * C_DIM + c0;
    asm volatile("red.global.add.v4.f32 [%0], {%1,%2,%3,%4};"
                 :: "l"(dstp), "f"(m0v), "f"(m1v), "f"(m2v), "f"(m3v) : "memory");
    asm volatile("red.global.add.v4.f32 [%0], {%1,%2,%3,%4};"
                 :: "l"(dstp + 4), "f"(m4v), "f"(m5v), "f"(m6v), "f"(m7v) : "memory");
}

// agg/max(cnt,1) -> f16; re-zeros agg for the next conv
__global__ void norm_agg_f16_kernel(float* __restrict__ agg,
                                    const float* __restrict__ cnt,
                                    f16* __restrict__ out, int n)
{
    int idx = blockIdx.x * blockDim.x + threadIdx.x;
    if (idx >= n * 64) return;
    int row = idx >> 6;
    float inv = 1.f / fmaxf(__ldg(cnt + row), 1.f);
    float4* ap = ((float4*)agg) + idx;
    float4 v = *ap;
    *ap = make_float4(0.f, 0.f, 0.f, 0.f);
    *(uint2*)(out + (size_t)idx * 4) =
        make_uint2(pack_h2(v.x * inv, v.y * inv), pack_h2(v.z * inv, v.w * inv));
}

// ---------------- host ----------------
extern "C" void kernel_launch(void* const* d_in, const int* in_sizes, int n_in,
                              void* d_out, int out_size)
{
    const float* x_user = (const float*)d_in[0];
    const float* x_item = (const float*)d_in[1];
    const float* pw1    = (const float*)d_in[2];
    const float* pb1    = (const float*)d_in[3];
    const float* pw2    = (const float*)d_in[4];
    const float* pb2    = (const float*)d_in[5];
    const float* msg_g  = (const float*)d_in[6];
    const float* msg_b  = (const float*)d_in[7];
    const float* lin_w  = (const float*)d_in[8];
    const float* lin_b  = (const float*)d_in[9];
    const float* node_g = (const float*)d_in[10];
    const float* node_b = (const float*)d_in[11];
    const int*   ei_ui  = (const int*)d_in[12];
    const int*   ei_iu  = (const int*)d_in[13];

    const int NUn = in_sizes[0] / C_DIM;
    const int NIn = in_sizes[1] / C_DIM;
    const int nE0 = in_sizes[12] / 2;
    const int nE1 = in_sizes[13] / 2;
    const int Lm = 2;

    float *aggb, *cnt_i, *cnt_u;
    f16 *xu_a, *xi_a, *xu_b, *xi_b, *h_f, *a_f, *p_f, *w_f;
    cudaGetSymbolAddress((void**)&aggb, g_agg);
    cudaGetSymbolAddress((void**)&cnt_i, g_cnt_i);
    cudaGetSymbolAddress((void**)&cnt_u, g_cnt_u);
    cudaGetSymbolAddress((void**)&xu_a, g_xu_a);
    cudaGetSymbolAddress((void**)&xi_a, g_xi_a);
    cudaGetSymbolAddress((void**)&xu_b, g_xu_b);
    cudaGetSymbolAddress((void**)&xi_b, g_xi_b);
    cudaGetSymbolAddress((void**)&h_f, g_h_f);
    cudaGetSymbolAddress((void**)&a_f, g_a_f);
    cudaGetSymbolAddress((void**)&p_f, g_p_f);
    cudaGetSymbolAddress((void**)&w_f, g_w);

    cudaFuncSetAttribute(gemm_h<0>, cudaFuncAttributeMaxDynamicSharedMemorySize, GEMM_SMEM);
    cudaFuncSetAttribute(gemm_h<1>, cudaFuncAttributeMaxDynamicSharedMemorySize, GEMM_SMEM);
    cudaFuncSetAttribute(gemm_ln, cudaFuncAttributeMaxDynamicSharedMemorySize, FUSED_SMEM);

    // weights: per conv t -> W1T | W2T | WCAT
    for (int t = 0; t < 4; t++) {
        size_t wo = (size_t)t * WSTRIDE;
        convert_w256_kernel<<<256, 256>>>(pw1 + (size_t)t * 65536, w_f + wo);
        convert_w256_kernel<<<256, 256>>>(pw2 + (size_t)t * 65536, w_f + wo + 65536);
        convert_w512_kernel<<<512, 256>>>(lin_w + (size_t)t * 131072, w_f + wo + 131072);
    }
    f32_to_f16_kernel<<<(NUn * 64 + 255) / 256, 256>>>(x_user, xu_a, NUn * 64);
    f32_to_f16_kernel<<<(NIn * 64 + 255) / 256, 256>>>(x_item, xi_a, NIn * 64);

    cudaMemsetAsync(cnt_i, 0, (size_t)NIn * sizeof(float));
    cudaMemsetAsync(cnt_u, 0, (size_t)NUn * sizeof(float));
    count_kernel<<<(nE0 + 255) / 256, 256>>>(ei_ui + nE0, cnt_i, nE0);
    count_kernel<<<(nE1 + 255) / 256, 256>>>(ei_iu + nE1, cnt_u, nE1);

    // agg zero once; norm_agg re-zeros after each use
    cudaMemsetAsync(aggb, 0, (size_t)MAXN * C_DIM * sizeof(float));

    float* out_f = (float*)d_out;
    f16* xu_cur = xu_a; f16* xi_cur = xi_a;
    f16* xu_nxt = xu_b; f16* xi_nxt = xi_b;

    for (int l = 0; l < Lm; l++) {
        bool last = (l == Lm - 1);
        // ---- conv: dst = item, src = user (params [l,0]) ----
        {
            int t = l * 2 + 0;
            size_t wo = (size_t)t * WSTRIDE;
            dim3 g2((NIn + 127) / 128, 2);
            gemm_h<1><<<g2, 256, GEMM_SMEM>>>(xi_cur, w_f + wo,
                pb1 + (size_t)t * C_DIM, h_f, NIn);
            gemm_h<0><<<g2, 256, GEMM_SMEM>>>(h_f, w_f + wo + 65536,
                pb2 + (size_t)t * C_DIM, p_f, NIn);
            edge_msg_kernel<<<(nE0 * 32 + 255) / 256, 256>>>(xu_cur, p_f, ei_ui,
                msg_g + (size_t)t * C_DIM, msg_b + (size_t)t * C_DIM, aggb, nE0);
            norm_agg_f16_kernel<<<(NIn * 64 + 255) / 256, 256>>>(aggb, cnt_i, a_f, NIn);
            gemm_ln<<<(NIn + 127) / 128, 512, FUSED_SMEM>>>(xi_cur, a_f,
                w_f + wo + 131072, lin_b + (size_t)t * C_DIM,
                node_g + (size_t)(l * 2 + 1) * C_DIM, node_b + (size_t)(l * 2 + 1) * C_DIM,
                last ? (out_f + (size_t)NUn * C_DIM) : (float*)0,
                last ? (f16*)0 : xi_nxt, NIn);
        }
        // ---- conv: dst = user, src = item (params [l,1]) ----
        {
            int t = l * 2 + 1;
            size_t wo = (size_t)t * WSTRIDE;
            dim3 g2((NUn + 127) / 128, 2);
            gemm_h<1><<<g2, 256, GEMM_SMEM>>>(xu_cur, w_f + wo,
                pb1 + (size_t)t * C_DIM, h_f, NUn);
            gemm_h<0><<<g2, 256, GEMM_SMEM>>>(h_f, w_f + wo + 65536,
                pb2 + (size_t)t * C_DIM, p_f, NUn);
            edge_msg_kernel<<<(nE1 * 32 + 255) / 256, 256>>>(xi_cur, p_f, ei_iu,
                msg_g + (size_t)t * C_DIM, msg_b + (size_t)t * C_DIM, aggb, nE1);
            norm_agg_f16_kernel<<<(NUn * 64 + 255) / 256, 256>>>(aggb, cnt_u, a_f, NUn);
            gemm_ln<<<(NUn + 127) / 128, 512, FUSED_SMEM>>>(xu_cur, a_f,
                w_f + wo + 131072, lin_b + (size_t)t * C_DIM,
                node_g + (size_t)(l * 2 + 0) * C_DIM, node_b + (size_t)(l * 2 + 0) * C_DIM,
                last ? out_f : (float*)0,
                last ? (f16*)0 : xu_nxt, NUn);
        }
        // swap feature buffers
        f16* tu = xu_cur; xu_cur = xu_nxt; xu_nxt = tu;
        f16* ti = xi_cur; xi_cur = xi_nxt; xi_nxt = ti;
    }
    (void)n_in; (void)out_size;
}